// round 9
// baseline (speedup 1.0000x reference)
#include <cuda_runtime.h>
#include <cstdint>

// ---------------- problem constants ----------------
namespace {
constexpr int BB = 2, SS = 2048, DD = 2048, HH = 16, GG = 4, HD = 128;
constexpr float EPS = 1e-6f;
constexpr float SCALING = 0.08838834764831845f; // 1/sqrt(128)

// GEMM pipeline config: 128x128 CTA tile, 4 warps (64x64 each), 3-stage cp.async
constexpr int NSTAGE = 3;
constexpr int ROWPAD = 36;                           // floats per row (144B, 16B-aligned)
constexpr uint32_t TILE_BYTES = 128 * ROWPAD * 4;    // 18432 per matrix
constexpr uint32_t STAGE_BYTES = 2 * TILE_BYTES;     // A + B = 36864
constexpr uint32_t GEMM_SMEM = NSTAGE * STAGE_BYTES; // 110592

// attention smem: 2-stage cp.async K/V double buffer (raw fp32)
constexpr int PADK = 132, PADV = 136, PADQ = 132;
constexpr uint32_t KBYTES = 64 * PADK * 4;           // 33792
constexpr uint32_t VBYTES = 64 * PADV * 4;           // 34816
constexpr uint32_t KVSTAGE = KBYTES + VBYTES;        // 68608
constexpr uint32_t ATTN_SMEM = 2 * KVSTAGE;          // 137216 (Q staged in stage-1 region)
}

// ---------------- scratch (device globals; no allocation allowed) ----------------
__device__ float g_q[(size_t)BB * HH * SS * HD];   // [B,H,S,HD]
__device__ float g_k[(size_t)BB * GG * SS * HD];   // [B,G,S,HD]
__device__ float g_v[(size_t)BB * GG * SS * HD];   // [B,G,S,HD]
__device__ float g_ctx[(size_t)BB * SS * HH * HD]; // [B,S,H*HD]

// ---------------- helpers ----------------
__device__ __forceinline__ uint32_t f2tf(float f) {
    uint32_t u;
    asm("cvt.rna.tf32.f32 %0, %1;" : "=r"(u) : "f"(f));
    return u;
}

__device__ __forceinline__ uint32_t f2tf_u(uint32_t x) {
    uint32_t u;
    asm("cvt.rna.tf32.f32 %0, %1;" : "=r"(u) : "r"(x));
    return u;
}

__device__ __forceinline__ void mma8(float* c, const uint32_t* a, const uint32_t* b) {
    asm volatile(
        "mma.sync.aligned.m16n8k8.row.col.f32.tf32.tf32.f32 "
        "{%0,%1,%2,%3},{%4,%5,%6,%7},{%8,%9},{%0,%1,%2,%3};\n"
        : "+f"(c[0]), "+f"(c[1]), "+f"(c[2]), "+f"(c[3])
        : "r"(a[0]), "r"(a[1]), "r"(a[2]), "r"(a[3]), "r"(b[0]), "r"(b[1]));
}

__device__ __forceinline__ uint32_t smem_u32(const void* p) {
    uint32_t a;
    asm("{ .reg .u64 t; cvta.to.shared.u64 t, %1; cvt.u32.u64 %0, t; }" : "=r"(a) : "l"(p));
    return a;
}

__device__ __forceinline__ void cpasync16(uint32_t dst, const void* src) {
    asm volatile("cp.async.cg.shared.global [%0], [%1], 16;" :: "r"(dst), "l"(src));
}

// =====================================================================
// GEMM: C[M,N] = A[M,K] * W[N,K]^T  (tf32 mma.sync, fp32 accum)
// CTA 128x128x32-slice, 128 threads, 4 warps each 64x64, 3-stage cp.async.
// mode 0: C row-major [M,N].  mode 1: head layout dst[b, bn, s, :].
// (PROVEN R4 text, unchanged.)
// =====================================================================
__global__ __launch_bounds__(128) void gemm_ws(
    const float* __restrict__ A, const float* __restrict__ W,
    float* __restrict__ Cout, int N, int K, int mode, int HN) {
    extern __shared__ float smem[];
    const int tid = threadIdx.x;
    const int lane = tid & 31, wid = tid >> 5;
    const int wm = wid & 1, wn = wid >> 1;
    const int g = lane >> 2, t = lane & 3;
    const int bm = blockIdx.y, bn = blockIdx.x;

    const float* Ag = A + (size_t)bm * 128 * K;
    const float* Wg = W + (size_t)bn * 128 * K;
    const int nk = K / 32;

    const uint32_t sb = smem_u32(smem);

    float acc[4][8][4];
#pragma unroll
    for (int i = 0; i < 4; i++)
#pragma unroll
        for (int j = 0; j < 8; j++)
#pragma unroll
            for (int q = 0; q < 4; q++) acc[i][j][q] = 0.f;

    // 16 cp.async per thread per stage (8 A-chunks + 8 B-chunks of 16B)
    auto loadstage = [&](int kt) {
        if (kt < nk) {
            const uint32_t sa = sb + (uint32_t)(kt % NSTAGE) * STAGE_BYTES;
            const uint32_t sw = sa + TILE_BYTES;
#pragma unroll
            for (int j = 0; j < 8; j++) {
                const int cc = tid + 128 * j;      // 0..1023
                const int row = cc >> 3, c16 = cc & 7;
                const uint32_t off = (uint32_t)row * (ROWPAD * 4) + c16 * 16;
                cpasync16(sa + off, Ag + (size_t)row * K + kt * 32 + c16 * 4);
                cpasync16(sw + off, Wg + (size_t)row * K + kt * 32 + c16 * 4);
            }
        }
        asm volatile("cp.async.commit_group;" ::: "memory");
    };

    loadstage(0);
    loadstage(1);

    for (int kt = 0; kt < nk; kt++) {
        asm volatile("cp.async.wait_group 1;" ::: "memory");
        __syncthreads();
        loadstage(kt + 2);  // writes slot (kt+2)%3 == (kt-1)%3, free since last sync

        const float* As = smem + (size_t)(kt % NSTAGE) * (STAGE_BYTES / 4);
        const float* Bs = As + TILE_BYTES / 4;

#pragma unroll
        for (int ks = 0; ks < 4; ks++) {
            uint32_t af[4][4], bf[8][2];
            const int c = ks * 8 + t;
#pragma unroll
            for (int mf = 0; mf < 4; mf++) {
                const int r = wm * 64 + mf * 16;
                af[mf][0] = f2tf_u(__float_as_uint(As[(r + g) * ROWPAD + c]));
                af[mf][1] = f2tf_u(__float_as_uint(As[(r + g + 8) * ROWPAD + c]));
                af[mf][2] = f2tf_u(__float_as_uint(As[(r + g) * ROWPAD + c + 4]));
                af[mf][3] = f2tf_u(__float_as_uint(As[(r + g + 8) * ROWPAD + c + 4]));
            }
#pragma unroll
            for (int nf = 0; nf < 8; nf++) {
                const int r = wn * 64 + nf * 8 + g;
                bf[nf][0] = f2tf_u(__float_as_uint(Bs[r * ROWPAD + c]));
                bf[nf][1] = f2tf_u(__float_as_uint(Bs[r * ROWPAD + c + 4]));
            }
#pragma unroll
            for (int mf = 0; mf < 4; mf++)
#pragma unroll
                for (int nf = 0; nf < 8; nf++)
                    mma8(acc[mf][nf], af[mf], bf[nf]);
        }
    }

    // ---- epilogue ----
#pragma unroll
    for (int mf = 0; mf < 4; mf++) {
#pragma unroll
        for (int nf = 0; nf < 8; nf++) {
            const int row = bm * 128 + wm * 64 + mf * 16 + g;
            const int col = bn * 128 + wn * 64 + nf * 8 + 2 * t;
#pragma unroll
            for (int half = 0; half < 2; half++) {
                const int rr = row + half * 8;
                float2 val = make_float2(acc[mf][nf][half * 2], acc[mf][nf][half * 2 + 1]);
                if (mode == 0) {
                    *(float2*)(Cout + (size_t)rr * N + col) = val;
                } else {
                    const int b = rr >> 11, s = rr & (SS - 1);
                    const int h = col >> 7, hd = col & 127;
                    *(float2*)(Cout + ((size_t)(b * HN + h) * SS + s) * HD + hd) = val;
                }
            }
        }
    }
}

// =====================================================================
// Fused RMSNorm + RoPE (+ q scaling), in place. One warp per (b,head,s) row.
// =====================================================================
__global__ __launch_bounds__(256) void rmsrope(
    const float* __restrict__ cosb, const float* __restrict__ sinb,
    const float* __restrict__ qw, const float* __restrict__ kw) {
    const int wid = threadIdx.x >> 5, lane = threadIdx.x & 31;
    const int row = blockIdx.x * 8 + wid;
    constexpr int QROWS = BB * HH * SS;

    float* base;
    const float* w;
    float extra;
    int s;
    if (row < QROWS) {
        base = g_q + (size_t)row * HD;
        w = qw;
        extra = SCALING;
        s = row & (SS - 1);
    } else {
        const int r = row - QROWS;
        base = g_k + (size_t)r * HD;
        w = kw;
        extra = 1.0f;
        s = r & (SS - 1);
    }

    float x0 = base[lane], x1 = base[lane + 32], x2 = base[lane + 64], x3 = base[lane + 96];
    float ssq = x0 * x0 + x1 * x1 + x2 * x2 + x3 * x3;
#pragma unroll
    for (int o = 16; o; o >>= 1) ssq += __shfl_xor_sync(0xffffffffu, ssq, o);
    const float inv = rsqrtf(ssq * (1.0f / HD) + EPS);

    const float n0 = x0 * inv * w[lane];
    const float n1 = x1 * inv * w[lane + 32];
    const float n2 = x2 * inv * w[lane + 64];
    const float n3 = x3 * inv * w[lane + 96];

    const float* cs = cosb + (size_t)s * HD;
    const float* sn = sinb + (size_t)s * HD;
    const float o0 = n0 * cs[lane] - n2 * sn[lane];
    const float o1 = n1 * cs[lane + 32] - n3 * sn[lane + 32];
    const float o2 = n2 * cs[lane + 64] + n0 * sn[lane + 64];
    const float o3 = n3 * cs[lane + 96] + n1 * sn[lane + 96];

    base[lane] = o0 * extra;
    base[lane + 32] = o1 * extra;
    base[lane + 64] = o2 * extra;
    base[lane + 96] = o3 * extra;
}

// =====================================================================
// Flash attention (causal). CTA = 128 q rows x one (b,h). 8 warps, each owns
// 16 q rows. Double-buffered cp.async K/V pipeline. Raw fp32 staged in smem;
// cvt.rna.tf32 applied at fragment read (same rounding as the proven R4 path).
// Loader covers the FULL 64x128 tile: 2048 16B-chunks = 8 per thread per matrix.
// =====================================================================
__global__ __launch_bounds__(256, 1) void attn() {
    extern __shared__ uint32_t sm[];
    const int tid = threadIdx.x;
    const int lane = tid & 31, wid = tid >> 5;
    const int g = lane >> 2, t = lane & 3;
    const uint32_t sb = smem_u32(sm);

    const int qt = gridDim.x - 1 - blockIdx.x;   // big tiles first
    const int bh = blockIdx.y;
    const int b = bh / HH, h = bh % HH;
    const int kvh = h / (HH / GG);

    const float* qp = g_q + ((size_t)(b * HH + h) * SS + qt * 128) * HD;
    const float* kp = g_k + ((size_t)(b * GG + kvh) * SS) * HD;
    const float* vp = g_v + ((size_t)(b * GG + kvh) * SS) * HD;

    // issue cp.async for K/V tile jt into stage st.
    // FULL tile: 64 rows x 128 cols x 4B = 32KB per matrix = 2048 chunks of 16B
    // -> 8 chunks per thread per matrix (cc = tid + 256*i, row = cc>>5, col16 = cc&31).
    auto issue_kv = [&](int jt, int st) {
        const uint32_t kb = sb + (uint32_t)st * KVSTAGE;
        const uint32_t vb = kb + KBYTES;
#pragma unroll
        for (int i = 0; i < 8; i++) {
            const int cc = tid + 256 * i;        // 0..2047
            const int row = cc >> 5, c16 = cc & 31;
            cpasync16(kb + (uint32_t)row * (PADK * 4) + c16 * 16,
                      kp + (size_t)(jt * 64 + row) * HD + c16 * 4);
            cpasync16(vb + (uint32_t)row * (PADV * 4) + c16 * 16,
                      vp + (size_t)(jt * 64 + row) * HD + c16 * 4);
        }
    };

    // preload K/V tile 0 into stage 0
    issue_kv(0, 0);
    asm volatile("cp.async.commit_group;" ::: "memory");

    // ---- stage Q tile (128x128, tf32) in the stage-1 region, grab frags ----
    uint32_t* Qs = sm + KVSTAGE / 4;
    {
        const int qr = tid >> 5;
        const int qc = (tid & 31) * 4;
#pragma unroll
        for (int i = 0; i < 16; i++) {
            const int rr = qr + i * 8;
            float4 v4 = *(const float4*)(qp + (size_t)rr * HD + qc);
            Qs[rr * PADQ + qc + 0] = f2tf(v4.x);
            Qs[rr * PADQ + qc + 1] = f2tf(v4.y);
            Qs[rr * PADQ + qc + 2] = f2tf(v4.z);
            Qs[rr * PADQ + qc + 3] = f2tf(v4.w);
        }
    }
    __syncthreads();

    uint32_t qf[16][4];
    {
        const int r = wid * 16;
#pragma unroll
        for (int ks = 0; ks < 16; ks++) {
            qf[ks][0] = Qs[(r + g) * PADQ + ks * 8 + t];
            qf[ks][1] = Qs[(r + g + 8) * PADQ + ks * 8 + t];
            qf[ks][2] = Qs[(r + g) * PADQ + ks * 8 + t + 4];
            qf[ks][3] = Qs[(r + g + 8) * PADQ + ks * 8 + t + 4];
        }
    }
    __syncthreads();   // stage-1 region now free for K/V tile 1

    float o[16][4];
#pragma unroll
    for (int i = 0; i < 16; i++)
#pragma unroll
        for (int j = 0; j < 4; j++) o[i][j] = 0.f;
    float mprev[2] = {-1e30f, -1e30f};
    float lsum[2] = {0.f, 0.f};

    const int jmax = 2 * qt + 1;
    for (int jt = 0; jt <= jmax; jt++) {
        // prefetch next tile into the other stage
        if (jt + 1 <= jmax) issue_kv(jt + 1, (jt + 1) & 1);
        asm volatile("cp.async.commit_group;" ::: "memory");
        asm volatile("cp.async.wait_group 1;" ::: "memory");  // tile jt resident
        __syncthreads();

        const uint32_t* Ks = sm + (size_t)(jt & 1) * (KVSTAGE / 4);
        const uint32_t* Vs = Ks + KBYTES / 4;

        // ---- scores = Q K^T (64 kv cols per tile) ----
        float sc[8][4];
#pragma unroll
        for (int i = 0; i < 8; i++)
#pragma unroll
            for (int j = 0; j < 4; j++) sc[i][j] = 0.f;

#pragma unroll
        for (int ks = 0; ks < 16; ks++) {
#pragma unroll
            for (int nf = 0; nf < 8; nf++) {
                uint32_t bfr[2];
                bfr[0] = f2tf_u(Ks[(nf * 8 + g) * PADK + ks * 8 + t]);
                bfr[1] = f2tf_u(Ks[(nf * 8 + g) * PADK + ks * 8 + t + 4]);
                mma8(sc[nf], qf[ks], bfr);
            }
        }

        // ---- causal mask (diagonal tiles only) ----
        if (jt >= 2 * qt) {
            const int rowg = qt * 128 + wid * 16 + g;
#pragma unroll
            for (int nf = 0; nf < 8; nf++) {
                const int colg = jt * 64 + nf * 8 + 2 * t;
                if (colg > rowg) sc[nf][0] = -1e30f;
                if (colg + 1 > rowg) sc[nf][1] = -1e30f;
                if (colg > rowg + 8) sc[nf][2] = -1e30f;
                if (colg + 1 > rowg + 8) sc[nf][3] = -1e30f;
            }
        }

        // ---- online softmax (rows g and g+8; quad reduce) ----
#pragma unroll
        for (int r = 0; r < 2; r++) {
            float mx = -1e30f;
#pragma unroll
            for (int nf = 0; nf < 8; nf++)
                mx = fmaxf(mx, fmaxf(sc[nf][2 * r], sc[nf][2 * r + 1]));
            mx = fmaxf(mx, __shfl_xor_sync(0xffffffffu, mx, 1));
            mx = fmaxf(mx, __shfl_xor_sync(0xffffffffu, mx, 2));
            const float mnew = fmaxf(mprev[r], mx);
            const float corr = __expf(mprev[r] - mnew);
            float sum = 0.f;
#pragma unroll
            for (int nf = 0; nf < 8; nf++) {
                sc[nf][2 * r] = __expf(sc[nf][2 * r] - mnew);
                sc[nf][2 * r + 1] = __expf(sc[nf][2 * r + 1] - mnew);
                sum += sc[nf][2 * r] + sc[nf][2 * r + 1];
            }
            sum += __shfl_xor_sync(0xffffffffu, sum, 1);
            sum += __shfl_xor_sync(0xffffffffu, sum, 2);
            lsum[r] = lsum[r] * corr + sum;
            mprev[r] = mnew;
#pragma unroll
            for (int nf = 0; nf < 16; nf++) {
                o[nf][2 * r] *= corr;
                o[nf][2 * r + 1] *= corr;
            }
        }

        // ---- O += P V : P C-frags -> A-frags via intra-quad shuffles ----
#pragma unroll
        for (int ks = 0; ks < 8; ks++) {
            const int qb = lane & ~3;
            const int s0 = qb | (t >> 1);
            const int s1 = s0 + 2;
            const float x0 = __shfl_sync(0xffffffffu, sc[ks][0], s0);
            const float x1 = __shfl_sync(0xffffffffu, sc[ks][1], s0);
            const float y0 = __shfl_sync(0xffffffffu, sc[ks][0], s1);
            const float y1 = __shfl_sync(0xffffffffu, sc[ks][1], s1);
            const float z0 = __shfl_sync(0xffffffffu, sc[ks][2], s0);
            const float z1 = __shfl_sync(0xffffffffu, sc[ks][3], s0);
            const float w0 = __shfl_sync(0xffffffffu, sc[ks][2], s1);
            const float w1 = __shfl_sync(0xffffffffu, sc[ks][3], s1);
            const bool odd = (t & 1);
            uint32_t pafr[4];
            pafr[0] = f2tf(odd ? x1 : x0);
            pafr[1] = f2tf(odd ? z1 : z0);
            pafr[2] = f2tf(odd ? y1 : y0);
            pafr[3] = f2tf(odd ? w1 : w0);
#pragma unroll
            for (int nf = 0; nf < 16; nf++) {
                uint32_t bfr[2];
                bfr[0] = f2tf_u(Vs[(ks * 8 + t) * PADV + nf * 8 + g]);
                bfr[1] = f2tf_u(Vs[(ks * 8 + t + 4) * PADV + nf * 8 + g]);
                mma8(o[nf], pafr, bfr);
            }
        }
        __syncthreads();   // all warps done with stage jt&1 before next overwrite
    }

    // ---- epilogue: O/l -> ctx [B,S,H*HD] ----
    const float inv0 = 1.f / lsum[0];
    const float inv1 = 1.f / lsum[1];
    const int row0 = qt * 128 + wid * 16 + g;
#pragma unroll
    for (int nf = 0; nf < 16; nf++) {
        const int col = nf * 8 + 2 * t;
        *(float2*)(g_ctx + ((size_t)(b * SS + row0) * (HH * HD)) + h * HD + col) =
            make_float2(o[nf][0] * inv0, o[nf][1] * inv0);
        *(float2*)(g_ctx + ((size_t)(b * SS + row0 + 8) * (HH * HD)) + h * HD + col) =
            make_float2(o[nf][2] * inv1, o[nf][3] * inv1);
    }
}

// =====================================================================
// host launcher
// =====================================================================
extern "C" void kernel_launch(void* const* d_in, const int* in_sizes, int n_in,
                              void* d_out, int out_size) {
    (void)in_sizes; (void)n_in; (void)out_size;
    const float* x    = (const float*)d_in[0];
    // d_in[1] = mask (causal triu, known analytically; unused)
    const float* cosb = (const float*)d_in[2];
    const float* sinb = (const float*)d_in[3];
    const float* Wq   = (const float*)d_in[4];
    const float* Wk   = (const float*)d_in[5];
    const float* Wv   = (const float*)d_in[6];
    const float* Wo   = (const float*)d_in[7];
    const float* qw   = (const float*)d_in[8];
    const float* kw   = (const float*)d_in[9];
    float* out = (float*)d_out;

    float *qptr, *kptr, *vptr, *cptr;
    cudaGetSymbolAddress((void**)&qptr, g_q);
    cudaGetSymbolAddress((void**)&kptr, g_k);
    cudaGetSymbolAddress((void**)&vptr, g_v);
    cudaGetSymbolAddress((void**)&cptr, g_ctx);

    cudaFuncSetAttribute(gemm_ws, cudaFuncAttributeMaxDynamicSharedMemorySize, GEMM_SMEM);
    cudaFuncSetAttribute(attn, cudaFuncAttributeMaxDynamicSharedMemorySize, ATTN_SMEM);

    // QKV projections (head-layout epilogue)
    gemm_ws<<<dim3(16, 32), 128, GEMM_SMEM>>>(x, Wq, qptr, HH * HD, DD, 1, HH);
    gemm_ws<<<dim3(4, 32), 128, GEMM_SMEM>>>(x, Wk, kptr, GG * HD, DD, 1, GG);
    gemm_ws<<<dim3(4, 32), 128, GEMM_SMEM>>>(x, Wv, vptr, GG * HD, DD, 1, GG);
    // RMSNorm + RoPE (+ q scaling), in place on q and k
    rmsrope<<<(BB * (HH + GG) * SS) / 8, 256>>>(cosb, sinb, qw, kw);
    // flash attention
    attn<<<dim3(SS / 128, BB * HH), 256, ATTN_SMEM>>>();
    // output projection -> d_out
    gemm_ws<<<dim3(16, 32), 128, GEMM_SMEM>>>(cptr, Wo, out, DD, HH * HD, 0, 0);
}

// round 10
// speedup vs baseline: 1.1935x; 1.1935x over previous
#include <cuda_runtime.h>
#include <cstdint>

// ---------------- problem constants ----------------
namespace {
constexpr int BB = 2, SS = 2048, DD = 2048, HH = 16, GG = 4, HD = 128;
constexpr float EPS = 1e-6f;
constexpr float SCALING = 0.08838834764831845f; // 1/sqrt(128)

// GEMM pipeline config: 128x128 CTA tile, 4 warps (64x64 each), 3-stage cp.async
constexpr int NSTAGE = 3;
constexpr int ROWPAD = 36;                           // floats per row (144B, 16B-aligned)
constexpr uint32_t TILE_BYTES = 128 * ROWPAD * 4;    // 18432 per matrix
constexpr uint32_t STAGE_BYTES = 2 * TILE_BYTES;     // A + B = 36864
constexpr uint32_t GEMM_SMEM = NSTAGE * STAGE_BYTES; // 110592
}

// ---------------- scratch (device globals; no allocation allowed) ----------------
__device__ float g_q[(size_t)BB * HH * SS * HD];   // [B,H,S,HD]
__device__ float g_k[(size_t)BB * GG * SS * HD];   // [B,G,S,HD]
__device__ float g_v[(size_t)BB * GG * SS * HD];   // [B,G,S,HD]
__device__ float g_ctx[(size_t)BB * SS * HH * HD]; // [B,S,H*HD]

// ---------------- helpers ----------------
__device__ __forceinline__ uint32_t f2tf(float f) {
    uint32_t u;
    asm("cvt.rna.tf32.f32 %0, %1;" : "=r"(u) : "f"(f));
    return u;
}

// pack float2 -> half2 (.x in low 16 bits, .y in high), round-to-nearest-even
__device__ __forceinline__ uint32_t pack_h2(float2 v) {
    uint32_t r;
    asm("cvt.rn.f16x2.f32 %0, %1, %2;" : "=r"(r) : "f"(v.y), "f"(v.x));
    return r;
}

// tf32 m16n8k8 (attention path, unchanged numerics)
__device__ __forceinline__ void mma8(float* c, const uint32_t* a, const uint32_t* b) {
    asm volatile(
        "mma.sync.aligned.m16n8k8.row.col.f32.tf32.tf32.f32 "
        "{%0,%1,%2,%3},{%4,%5,%6,%7},{%8,%9},{%0,%1,%2,%3};\n"
        : "+f"(c[0]), "+f"(c[1]), "+f"(c[2]), "+f"(c[3])
        : "r"(a[0]), "r"(a[1]), "r"(a[2]), "r"(a[3]), "r"(b[0]), "r"(b[1]));
}

// fp16 m16n8k16, fp32 accumulate (GEMM path)
__device__ __forceinline__ void mma16(float* c, const uint32_t* a, const uint32_t* b) {
    asm volatile(
        "mma.sync.aligned.m16n8k16.row.col.f32.f16.f16.f32 "
        "{%0,%1,%2,%3},{%4,%5,%6,%7},{%8,%9},{%0,%1,%2,%3};\n"
        : "+f"(c[0]), "+f"(c[1]), "+f"(c[2]), "+f"(c[3])
        : "r"(a[0]), "r"(a[1]), "r"(a[2]), "r"(a[3]), "r"(b[0]), "r"(b[1]));
}

__device__ __forceinline__ uint32_t smem_u32(const void* p) {
    uint32_t a;
    asm("{ .reg .u64 t; cvta.to.shared.u64 t, %1; cvt.u32.u64 %0, t; }" : "=r"(a) : "l"(p));
    return a;
}

__device__ __forceinline__ void cpasync16(uint32_t dst, const void* src) {
    asm volatile("cp.async.cg.shared.global [%0], [%1], 16;" :: "r"(dst), "l"(src));
}

// =====================================================================
// GEMM: C[M,N] = A[M,K] * W[N,K]^T  (fp16 m16n8k16 mma, fp32 accum)
// CTA 128x128x32-slice, 128 threads, 4 warps each 64x64, 3-stage cp.async.
// fp32 staged in smem (proven R4 loader); fragments packed to half2 at read.
// mode 0: C row-major [M,N].  mode 1: head layout dst[b, bn, s, :].
// =====================================================================
__global__ __launch_bounds__(128) void gemm_ws(
    const float* __restrict__ A, const float* __restrict__ W,
    float* __restrict__ Cout, int N, int K, int mode, int HN) {
    extern __shared__ float smem[];
    const int tid = threadIdx.x;
    const int lane = tid & 31, wid = tid >> 5;
    const int wm = wid & 1, wn = wid >> 1;
    const int g = lane >> 2, t = lane & 3;
    const int bm = blockIdx.y, bn = blockIdx.x;

    const float* Ag = A + (size_t)bm * 128 * K;
    const float* Wg = W + (size_t)bn * 128 * K;
    const int nk = K / 32;

    const uint32_t sb = smem_u32(smem);

    float acc[4][8][4];
#pragma unroll
    for (int i = 0; i < 4; i++)
#pragma unroll
        for (int j = 0; j < 8; j++)
#pragma unroll
            for (int q = 0; q < 4; q++) acc[i][j][q] = 0.f;

    // 16 cp.async per thread per stage (8 A-chunks + 8 B-chunks of 16B) — proven R4 loader
    auto loadstage = [&](int kt) {
        if (kt < nk) {
            const uint32_t sa = sb + (uint32_t)(kt % NSTAGE) * STAGE_BYTES;
            const uint32_t sw = sa + TILE_BYTES;
#pragma unroll
            for (int j = 0; j < 8; j++) {
                const int cc = tid + 128 * j;      // 0..1023
                const int row = cc >> 3, c16 = cc & 7;
                const uint32_t off = (uint32_t)row * (ROWPAD * 4) + c16 * 16;
                cpasync16(sa + off, Ag + (size_t)row * K + kt * 32 + c16 * 4);
                cpasync16(sw + off, Wg + (size_t)row * K + kt * 32 + c16 * 4);
            }
        }
        asm volatile("cp.async.commit_group;" ::: "memory");
    };

    loadstage(0);
    loadstage(1);

    for (int kt = 0; kt < nk; kt++) {
        asm volatile("cp.async.wait_group 1;" ::: "memory");
        __syncthreads();
        loadstage(kt + 2);  // writes slot (kt+2)%3 == (kt-1)%3, free since last sync

        const float* As = smem + (size_t)(kt % NSTAGE) * (STAGE_BYTES / 4);
        const float* Bs = As + TILE_BYTES / 4;

        // two k16 steps per 32-col slice
#pragma unroll
        for (int ks2 = 0; ks2 < 2; ks2++) {
            uint32_t af[4][4], bf[8][2];
            const int c = ks2 * 16 + 2 * t;     // fragment cols {c, c+1} and {c+8, c+9}
#pragma unroll
            for (int mf = 0; mf < 4; mf++) {
                const int r = wm * 64 + mf * 16;
                af[mf][0] = pack_h2(*(const float2*)&As[(r + g) * ROWPAD + c]);
                af[mf][1] = pack_h2(*(const float2*)&As[(r + g + 8) * ROWPAD + c]);
                af[mf][2] = pack_h2(*(const float2*)&As[(r + g) * ROWPAD + c + 8]);
                af[mf][3] = pack_h2(*(const float2*)&As[(r + g + 8) * ROWPAD + c + 8]);
            }
#pragma unroll
            for (int nf = 0; nf < 8; nf++) {
                const int r = wn * 64 + nf * 8 + g;
                bf[nf][0] = pack_h2(*(const float2*)&Bs[r * ROWPAD + c]);
                bf[nf][1] = pack_h2(*(const float2*)&Bs[r * ROWPAD + c + 8]);
            }
#pragma unroll
            for (int mf = 0; mf < 4; mf++)
#pragma unroll
                for (int nf = 0; nf < 8; nf++)
                    mma16(acc[mf][nf], af[mf], bf[nf]);
        }
    }

    // ---- epilogue (unchanged: C fragment layout identical to tf32 path) ----
#pragma unroll
    for (int mf = 0; mf < 4; mf++) {
#pragma unroll
        for (int nf = 0; nf < 8; nf++) {
            const int row = bm * 128 + wm * 64 + mf * 16 + g;
            const int col = bn * 128 + wn * 64 + nf * 8 + 2 * t;
#pragma unroll
            for (int half = 0; half < 2; half++) {
                const int rr = row + half * 8;
                float2 val = make_float2(acc[mf][nf][half * 2], acc[mf][nf][half * 2 + 1]);
                if (mode == 0) {
                    *(float2*)(Cout + (size_t)rr * N + col) = val;
                } else {
                    const int b = rr >> 11, s = rr & (SS - 1);
                    const int h = col >> 7, hd = col & 127;
                    *(float2*)(Cout + ((size_t)(b * HN + h) * SS + s) * HD + hd) = val;
                }
            }
        }
    }
}

// =====================================================================
// Fused RMSNorm + RoPE (+ q scaling), in place. One warp per (b,head,s) row.
// =====================================================================
__global__ __launch_bounds__(256) void rmsrope(
    const float* __restrict__ cosb, const float* __restrict__ sinb,
    const float* __restrict__ qw, const float* __restrict__ kw) {
    const int wid = threadIdx.x >> 5, lane = threadIdx.x & 31;
    const int row = blockIdx.x * 8 + wid;
    constexpr int QROWS = BB * HH * SS;

    float* base;
    const float* w;
    float extra;
    int s;
    if (row < QROWS) {
        base = g_q + (size_t)row * HD;
        w = qw;
        extra = SCALING;
        s = row & (SS - 1);
    } else {
        const int r = row - QROWS;
        base = g_k + (size_t)r * HD;
        w = kw;
        extra = 1.0f;
        s = r & (SS - 1);
    }

    float x0 = base[lane], x1 = base[lane + 32], x2 = base[lane + 64], x3 = base[lane + 96];
    float ssq = x0 * x0 + x1 * x1 + x2 * x2 + x3 * x3;
#pragma unroll
    for (int o = 16; o; o >>= 1) ssq += __shfl_xor_sync(0xffffffffu, ssq, o);
    const float inv = rsqrtf(ssq * (1.0f / HD) + EPS);

    const float n0 = x0 * inv * w[lane];
    const float n1 = x1 * inv * w[lane + 32];
    const float n2 = x2 * inv * w[lane + 64];
    const float n3 = x3 * inv * w[lane + 96];

    const float* cs = cosb + (size_t)s * HD;
    const float* sn = sinb + (size_t)s * HD;
    const float o0 = n0 * cs[lane] - n2 * sn[lane];
    const float o1 = n1 * cs[lane + 32] - n3 * sn[lane + 32];
    const float o2 = n2 * cs[lane + 64] + n0 * sn[lane + 64];
    const float o3 = n3 * cs[lane + 96] + n1 * sn[lane + 96];

    base[lane] = o0 * extra;
    base[lane + 32] = o1 * extra;
    base[lane + 64] = o2 * extra;
    base[lane + 96] = o3 * extra;
}

// =====================================================================
// Flash attention (causal) — PROVEN R4 text, unchanged (tf32 path).
// CTA = 128 q rows x one (b,h). 8 warps, each owns 16 q rows.
// =====================================================================
namespace {
constexpr int PADQ = 132, PADK = 132, PADV = 136;
constexpr int SM_K = 64 * PADK;
constexpr int SM_V = 64 * PADV;
constexpr int SM_Q = 128 * PADQ;
constexpr int SM_TOT = (SM_K + SM_V > SM_Q) ? (SM_K + SM_V) : SM_Q;
}

__global__ __launch_bounds__(256, 1) void attn() {
    extern __shared__ uint32_t sm[];
    uint32_t* Qs = sm;
    uint32_t* Ks = sm;
    uint32_t* Vs = sm + SM_K;

    const int tid = threadIdx.x;
    const int lane = tid & 31, wid = tid >> 5;
    const int g = lane >> 2, t = lane & 3;

    const int qt = gridDim.x - 1 - blockIdx.x;   // big tiles first
    const int bh = blockIdx.y;
    const int b = bh / HH, h = bh % HH;
    const int kvh = h / (HH / GG);

    const float* qp = g_q + ((size_t)(b * HH + h) * SS + qt * 128) * HD;
    const float* kp = g_k + ((size_t)(b * GG + kvh) * SS) * HD;
    const float* vp = g_v + ((size_t)(b * GG + kvh) * SS) * HD;

    // ---- stage Q tile (128x128) into smem, converted to tf32 ----
    {
        const int qr = tid >> 5;
        const int qc = (tid & 31) * 4;
#pragma unroll
        for (int i = 0; i < 16; i++) {
            const int rr = qr + i * 8;
            float4 v4 = *(const float4*)(qp + (size_t)rr * HD + qc);
            Qs[rr * PADQ + qc + 0] = f2tf(v4.x);
            Qs[rr * PADQ + qc + 1] = f2tf(v4.y);
            Qs[rr * PADQ + qc + 2] = f2tf(v4.z);
            Qs[rr * PADQ + qc + 3] = f2tf(v4.w);
        }
    }
    __syncthreads();

    uint32_t qf[16][4];
    {
        const int r = wid * 16;
#pragma unroll
        for (int ks = 0; ks < 16; ks++) {
            qf[ks][0] = Qs[(r + g) * PADQ + ks * 8 + t];
            qf[ks][1] = Qs[(r + g + 8) * PADQ + ks * 8 + t];
            qf[ks][2] = Qs[(r + g) * PADQ + ks * 8 + t + 4];
            qf[ks][3] = Qs[(r + g + 8) * PADQ + ks * 8 + t + 4];
        }
    }
    __syncthreads();   // before K/V overwrite the Q staging region

    float o[16][4];
#pragma unroll
    for (int i = 0; i < 16; i++)
#pragma unroll
        for (int j = 0; j < 4; j++) o[i][j] = 0.f;
    float mprev[2] = {-1e30f, -1e30f};
    float lsum[2] = {0.f, 0.f};

    const int jmax = 2 * qt + 1;
    for (int jt = 0; jt <= jmax; jt++) {
        // ---- load K,V tile (64x128) ----
        {
            const int rr0 = tid >> 5;
            const int cc = (tid & 31) * 4;
#pragma unroll
            for (int i = 0; i < 8; i++) {
                const int rr = rr0 + i * 8;
                float4 kv4 = *(const float4*)(kp + (size_t)(jt * 64 + rr) * HD + cc);
                Ks[rr * PADK + cc + 0] = f2tf(kv4.x);
                Ks[rr * PADK + cc + 1] = f2tf(kv4.y);
                Ks[rr * PADK + cc + 2] = f2tf(kv4.z);
                Ks[rr * PADK + cc + 3] = f2tf(kv4.w);
                float4 vv4 = *(const float4*)(vp + (size_t)(jt * 64 + rr) * HD + cc);
                Vs[rr * PADV + cc + 0] = f2tf(vv4.x);
                Vs[rr * PADV + cc + 1] = f2tf(vv4.y);
                Vs[rr * PADV + cc + 2] = f2tf(vv4.z);
                Vs[rr * PADV + cc + 3] = f2tf(vv4.w);
            }
        }
        __syncthreads();

        // ---- scores = Q K^T (64 kv cols per tile) ----
        float sc[8][4];
#pragma unroll
        for (int i = 0; i < 8; i++)
#pragma unroll
            for (int j = 0; j < 4; j++) sc[i][j] = 0.f;

#pragma unroll
        for (int ks = 0; ks < 16; ks++) {
#pragma unroll
            for (int nf = 0; nf < 8; nf++) {
                uint32_t bfr[2];
                bfr[0] = Ks[(nf * 8 + g) * PADK + ks * 8 + t];
                bfr[1] = Ks[(nf * 8 + g) * PADK + ks * 8 + t + 4];
                mma8(sc[nf], qf[ks], bfr);
            }
        }

        // ---- causal mask (only the two diagonal tiles need it) ----
        if (jt >= 2 * qt) {
            const int rowg = qt * 128 + wid * 16 + g;
#pragma unroll
            for (int nf = 0; nf < 8; nf++) {
                const int colg = jt * 64 + nf * 8 + 2 * t;
                if (colg > rowg) sc[nf][0] = -1e30f;
                if (colg + 1 > rowg) sc[nf][1] = -1e30f;
                if (colg > rowg + 8) sc[nf][2] = -1e30f;
                if (colg + 1 > rowg + 8) sc[nf][3] = -1e30f;
            }
        }

        // ---- online softmax (per-thread rows g and g+8; quad reduce) ----
#pragma unroll
        for (int r = 0; r < 2; r++) {
            float mx = -1e30f;
#pragma unroll
            for (int nf = 0; nf < 8; nf++)
                mx = fmaxf(mx, fmaxf(sc[nf][2 * r], sc[nf][2 * r + 1]));
            mx = fmaxf(mx, __shfl_xor_sync(0xffffffffu, mx, 1));
            mx = fmaxf(mx, __shfl_xor_sync(0xffffffffu, mx, 2));
            const float mnew = fmaxf(mprev[r], mx);
            const float corr = __expf(mprev[r] - mnew);
            float sum = 0.f;
#pragma unroll
            for (int nf = 0; nf < 8; nf++) {
                sc[nf][2 * r] = __expf(sc[nf][2 * r] - mnew);
                sc[nf][2 * r + 1] = __expf(sc[nf][2 * r + 1] - mnew);
                sum += sc[nf][2 * r] + sc[nf][2 * r + 1];
            }
            sum += __shfl_xor_sync(0xffffffffu, sum, 1);
            sum += __shfl_xor_sync(0xffffffffu, sum, 2);
            lsum[r] = lsum[r] * corr + sum;
            mprev[r] = mnew;
#pragma unroll
            for (int nf = 0; nf < 16; nf++) {
                o[nf][2 * r] *= corr;
                o[nf][2 * r + 1] *= corr;
            }
        }

        // ---- O += P V : build A-frags of P via intra-quad shuffles ----
#pragma unroll
        for (int ks = 0; ks < 8; ks++) {
            const int qb = lane & ~3;
            const int s0 = qb | (t >> 1);
            const int s1 = s0 + 2;
            const float x0 = __shfl_sync(0xffffffffu, sc[ks][0], s0);
            const float x1 = __shfl_sync(0xffffffffu, sc[ks][1], s0);
            const float y0 = __shfl_sync(0xffffffffu, sc[ks][0], s1);
            const float y1 = __shfl_sync(0xffffffffu, sc[ks][1], s1);
            const float z0 = __shfl_sync(0xffffffffu, sc[ks][2], s0);
            const float z1 = __shfl_sync(0xffffffffu, sc[ks][3], s0);
            const float w0 = __shfl_sync(0xffffffffu, sc[ks][2], s1);
            const float w1 = __shfl_sync(0xffffffffu, sc[ks][3], s1);
            const bool odd = (t & 1);
            uint32_t pafr[4];
            pafr[0] = f2tf(odd ? x1 : x0);
            pafr[1] = f2tf(odd ? z1 : z0);
            pafr[2] = f2tf(odd ? y1 : y0);
            pafr[3] = f2tf(odd ? w1 : w0);
#pragma unroll
            for (int nf = 0; nf < 16; nf++) {
                uint32_t bfr[2];
                bfr[0] = Vs[(ks * 8 + t) * PADV + nf * 8 + g];
                bfr[1] = Vs[(ks * 8 + t + 4) * PADV + nf * 8 + g];
                mma8(o[nf], pafr, bfr);
            }
        }
        __syncthreads();   // protect K/V smem before next tile load
    }

    // ---- epilogue: O/l -> ctx [B,S,H*HD] ----
    const float inv0 = 1.f / lsum[0];
    const float inv1 = 1.f / lsum[1];
    const int row0 = qt * 128 + wid * 16 + g;
#pragma unroll
    for (int nf = 0; nf < 16; nf++) {
        const int col = nf * 8 + 2 * t;
        *(float2*)(g_ctx + ((size_t)(b * SS + row0) * (HH * HD)) + h * HD + col) =
            make_float2(o[nf][0] * inv0, o[nf][1] * inv0);
        *(float2*)(g_ctx + ((size_t)(b * SS + row0 + 8) * (HH * HD)) + h * HD + col) =
            make_float2(o[nf][2] * inv1, o[nf][3] * inv1);
    }
}

// =====================================================================
// host launcher
// =====================================================================
extern "C" void kernel_launch(void* const* d_in, const int* in_sizes, int n_in,
                              void* d_out, int out_size) {
    (void)in_sizes; (void)n_in; (void)out_size;
    const float* x    = (const float*)d_in[0];
    // d_in[1] = mask (causal triu, known analytically; unused)
    const float* cosb = (const float*)d_in[2];
    const float* sinb = (const float*)d_in[3];
    const float* Wq   = (const float*)d_in[4];
    const float* Wk   = (const float*)d_in[5];
    const float* Wv   = (const float*)d_in[6];
    const float* Wo   = (const float*)d_in[7];
    const float* qw   = (const float*)d_in[8];
    const float* kw   = (const float*)d_in[9];
    float* out = (float*)d_out;

    float *qptr, *kptr, *vptr, *cptr;
    cudaGetSymbolAddress((void**)&qptr, g_q);
    cudaGetSymbolAddress((void**)&kptr, g_k);
    cudaGetSymbolAddress((void**)&vptr, g_v);
    cudaGetSymbolAddress((void**)&cptr, g_ctx);

    cudaFuncSetAttribute(gemm_ws, cudaFuncAttributeMaxDynamicSharedMemorySize, GEMM_SMEM);
    cudaFuncSetAttribute(attn, cudaFuncAttributeMaxDynamicSharedMemorySize, SM_TOT * 4);

    // QKV projections (head-layout epilogue)
    gemm_ws<<<dim3(16, 32), 128, GEMM_SMEM>>>(x, Wq, qptr, HH * HD, DD, 1, HH);
    gemm_ws<<<dim3(4, 32), 128, GEMM_SMEM>>>(x, Wk, kptr, GG * HD, DD, 1, GG);
    gemm_ws<<<dim3(4, 32), 128, GEMM_SMEM>>>(x, Wv, vptr, GG * HD, DD, 1, GG);
    // RMSNorm + RoPE (+ q scaling), in place on q and k
    rmsrope<<<(BB * (HH + GG) * SS) / 8, 256>>>(cosb, sinb, qw, kw);
    // flash attention (tf32, proven R4 path)
    attn<<<dim3(SS / 128, BB * HH), 256, SM_TOT * 4>>>();
    // output projection -> d_out
    gemm_ws<<<dim3(16, 32), 128, GEMM_SMEM>>>(cptr, Wo, out, DD, HH * HD, 0, 0);
}